// round 7
// baseline (speedup 1.0000x reference)
#include <cuda_runtime.h>
#include <math.h>

#define NN   100000
#define NE   3200000
#define FIN  512
#define CD   64
#define KORD 10

// ---- static scratch (no allocations allowed) ----
__device__ int   g_idx64;              // 1 if edge_index is int64, 0 if int32
__device__ int   g_deg[NN];
__device__ int   g_off[NN + 1];
__device__ int   g_cur[NN];
__device__ float g_dinv[NN];
__device__ int2  g_edges[NE];          // {src, norm-as-bits}, grouped by dst
__device__ float g_Pa[(size_t)NN * CD];
__device__ float g_Pb[(size_t)NN * CD];
__device__ float g_ret[(size_t)NN * CD];

// ---------------- dtype probe ----------------
// If the buffer really holds int64 indices, every value is in [0, NN).
// If it holds int32 packed pairs read as int64, values are ~always >= 2^32.
__global__ void k_probe(const void* ei) {
    if (threadIdx.x == 0 && blockIdx.x == 0) {
        const long long* p = (const long long*)ei;
        int ok = 1;
        for (int i = 0; i < 256; i++) {
            long long v = p[i];
            if (v < 0 || v >= NN) { ok = 0; break; }
        }
        g_idx64 = ok;
    }
}

__device__ __forceinline__ int load_idx(const void* ei, long long i, int is64) {
    if (is64) return (int)((const long long*)ei)[i];
    return ((const int*)ei)[i];
}

// ---------------- setup kernels ----------------
__global__ void k_zero_deg() {
    int i = blockIdx.x * blockDim.x + threadIdx.x;
    if (i < NN) g_deg[i] = 0;
}

__global__ void k_deg(const void* __restrict__ ei) {
    int e = blockIdx.x * blockDim.x + threadIdx.x;
    int is64 = g_idx64;
    if (e < NE) {
        int c = load_idx(ei, (long long)NE + e, is64);   // col = second half
        atomicAdd(&g_deg[c], 1);
    }
}

__global__ void k_dinv() {
    int i = blockIdx.x * blockDim.x + threadIdx.x;
    if (i < NN) {
        int d = g_deg[i];
        g_dinv[i] = (d > 0) ? rsqrtf((float)d) : 1.0f;
    }
}

// single-block exclusive scan of g_deg -> g_off (and g_cur copy)
__global__ void k_scan() {
    __shared__ int wsum[32];
    __shared__ int srun;
    int tid = threadIdx.x, lane = tid & 31, wid = tid >> 5;
    if (tid == 0) srun = 0;
    __syncthreads();
    for (int base = 0; base < NN; base += 1024) {
        int i = base + tid;
        int v = (i < NN) ? g_deg[i] : 0;
        int x = v;
        #pragma unroll
        for (int d = 1; d < 32; d <<= 1) {
            int y = __shfl_up_sync(0xffffffffu, x, d);
            if (lane >= d) x += y;
        }
        if (lane == 31) wsum[wid] = x;
        __syncthreads();
        if (wid == 0) {
            int t = wsum[lane];
            #pragma unroll
            for (int d = 1; d < 32; d <<= 1) {
                int y = __shfl_up_sync(0xffffffffu, t, d);
                if (lane >= d) t += y;
            }
            wsum[lane] = t;
        }
        __syncthreads();
        int woff = wid ? wsum[wid - 1] : 0;
        int excl = srun + woff + (x - v);
        if (i < NN) { g_off[i] = excl; g_cur[i] = excl; }
        int btot = wsum[31];
        __syncthreads();
        if (tid == 0) srun += btot;
        __syncthreads();
    }
    if (tid == 0) g_off[NN] = srun;
}

__global__ void k_scatter(const void* __restrict__ ei) {
    int e = blockIdx.x * blockDim.x + threadIdx.x;
    int is64 = g_idx64;
    if (e < NE) {
        int r = load_idx(ei, e, is64);
        int c = load_idx(ei, (long long)NE + e, is64);
        float w = g_dinv[r] * g_dinv[c];
        int pos = atomicAdd(&g_cur[c], 1);
        g_edges[pos] = make_int2(r, __float_as_int(w));
    }
}

// ---------------- GEMM: h = x@W + b ; P0 = h ; ret = h * mf[0] ----------------
__global__ void k_gemm(const float* __restrict__ X, const float* __restrict__ W,
                       const float* __restrict__ bias, const float* __restrict__ mf) {
    __shared__ float As[32][64];
    __shared__ float Bs[32][64];
    int tid = threadIdx.x;
    int tx = tid & 15, ty = tid >> 4;
    int rowBase = blockIdx.x * 64;
    float acc[4][4];
    #pragma unroll
    for (int i = 0; i < 4; i++)
        #pragma unroll
        for (int j = 0; j < 4; j++) acc[i][j] = 0.f;

    for (int k0 = 0; k0 < FIN; k0 += 32) {
        #pragma unroll
        for (int i = 0; i < 2; i++) {
            int f  = tid * 2 + i;
            int r  = f >> 3;
            int kc = (f & 7) * 4;
            int rr = rowBase + r;
            if (rr >= NN) rr = NN - 1;
            float4 v = *(const float4*)&X[(size_t)rr * FIN + k0 + kc];
            As[kc + 0][r] = v.x; As[kc + 1][r] = v.y;
            As[kc + 2][r] = v.z; As[kc + 3][r] = v.w;
        }
        #pragma unroll
        for (int i = 0; i < 2; i++) {
            int f  = tid * 2 + i;
            int rk = f >> 4;
            int cc = (f & 15) * 4;
            *(float4*)&Bs[rk][cc] = *(const float4*)&W[(size_t)(k0 + rk) * CD + cc];
        }
        __syncthreads();
        #pragma unroll
        for (int kk = 0; kk < 32; kk++) {
            float4 a4 = *(const float4*)&As[kk][ty * 4];
            float4 b4 = *(const float4*)&Bs[kk][tx * 4];
            float a[4] = {a4.x, a4.y, a4.z, a4.w};
            float bb[4] = {b4.x, b4.y, b4.z, b4.w};
            #pragma unroll
            for (int i = 0; i < 4; i++)
                #pragma unroll
                for (int j = 0; j < 4; j++)
                    acc[i][j] += a[i] * bb[j];
        }
        __syncthreads();
    }
    #pragma unroll
    for (int i = 0; i < 4; i++) {
        int r = rowBase + ty * 4 + i;
        if (r < NN) {
            #pragma unroll
            for (int j = 0; j < 4; j++) {
                int c = tx * 4 + j;
                float h = acc[i][j] + bias[c];
                g_Pa[(size_t)r * CD + c]  = h;
                g_ret[(size_t)r * CD + c] = h * mf[c];  // coef for P0 is 1
            }
        }
    }
}

// ---------------- fused propagation + recurrence + accumulation ----------------
// warp per node; lane owns 2 channels (float2). CSR pull: fully coalesced gathers.
__global__ void k_prop(int n, const float* __restrict__ lap,
                       const float* __restrict__ mfw) {
    int gw   = (blockIdx.x * blockDim.x + threadIdx.x) >> 5;
    int lane = threadIdx.x & 31;
    if (gw >= NN) return;
    const float2* __restrict__ Pprev = (const float2*)((n & 1) ? g_Pa : g_Pb);
    float2* __restrict__ Pout        = (float2*)((n & 1) ? g_Pb : g_Pa);

    int beg = g_off[gw], end = g_off[gw + 1];
    float ax = 0.f, ay = 0.f;
    int e = beg;
    for (; e + 4 <= end; e += 4) {
        int2 m0 = g_edges[e];     int2 m1 = g_edges[e + 1];
        int2 m2 = g_edges[e + 2]; int2 m3 = g_edges[e + 3];
        float2 v0 = Pprev[(size_t)m0.x * 32 + lane];
        float2 v1 = Pprev[(size_t)m1.x * 32 + lane];
        float2 v2 = Pprev[(size_t)m2.x * 32 + lane];
        float2 v3 = Pprev[(size_t)m3.x * 32 + lane];
        float w0 = __int_as_float(m0.y), w1 = __int_as_float(m1.y);
        float w2 = __int_as_float(m2.y), w3 = __int_as_float(m3.y);
        ax = fmaf(w0, v0.x, ax); ay = fmaf(w0, v0.y, ay);
        ax = fmaf(w1, v1.x, ax); ay = fmaf(w1, v1.y, ay);
        ax = fmaf(w2, v2.x, ax); ay = fmaf(w2, v2.y, ay);
        ax = fmaf(w3, v3.x, ax); ay = fmaf(w3, v3.y, ay);
    }
    for (; e < end; e++) {
        int2 m = g_edges[e];
        float2 v = Pprev[(size_t)m.x * 32 + lane];
        float w = __int_as_float(m.y);
        ax = fmaf(w, v.x, ax); ay = fmaf(w, v.y, ay);
    }

    size_t idx = (size_t)gw * 32 + lane;
    float px, py;
    if (n == 1) { px = ax; py = ay; }
    else {
        float2 old = Pout[idx];                 // holds P_{n-2}
        px = 2.f * ax - old.x;
        py = 2.f * ay - old.y;
    }
    Pout[idx] = make_float2(px, py);

    float coef = __ldg(&lap[n - 1]);
    float2 mfv = ((const float2*)(mfw + (size_t)n * CD))[lane];
    float2 r = ((float2*)g_ret)[idx];
    r.x = fmaf(coef * mfv.x, px, r.x);
    r.y = fmaf(coef * mfv.y, py, r.y);
    ((float2*)g_ret)[idx] = r;
}

// ---------------- log_softmax ----------------
__global__ void k_softmax(float* __restrict__ out) {
    int gw   = (blockIdx.x * blockDim.x + threadIdx.x) >> 5;
    int lane = threadIdx.x & 31;
    if (gw >= NN) return;
    size_t idx = (size_t)gw * 32 + lane;
    float2 v = ((const float2*)g_ret)[idx];
    float m = fmaxf(v.x, v.y);
    #pragma unroll
    for (int d = 16; d > 0; d >>= 1)
        m = fmaxf(m, __shfl_xor_sync(0xffffffffu, m, d));
    float s = expf(v.x - m) + expf(v.y - m);
    #pragma unroll
    for (int d = 16; d > 0; d >>= 1)
        s += __shfl_xor_sync(0xffffffffu, s, d);
    float lse = m + logf(s);
    ((float2*)out)[idx] = make_float2(v.x - lse, v.y - lse);
}

// ---------------- launch ----------------
extern "C" void kernel_launch(void* const* d_in, const int* in_sizes, int n_in,
                              void* d_out, int out_size) {
    const float* x   = (const float*)d_in[0];
    const void*  ei  = d_in[1];
    const float* W   = (const float*)d_in[2];
    const float* b   = (const float*)d_in[3];
    const float* lap = (const float*)d_in[4];
    const float* mf  = (const float*)d_in[5];
    float*       out = (float*)d_out;

    k_probe<<<1, 32>>>(ei);
    k_zero_deg<<<(NN + 255) / 256, 256>>>();
    k_deg<<<NE / 256, 256>>>(ei);
    k_dinv<<<(NN + 255) / 256, 256>>>();
    k_scan<<<1, 1024>>>();
    k_scatter<<<NE / 256, 256>>>(ei);
    k_gemm<<<(NN + 63) / 64, 256>>>(x, W, b, mf);
    for (int n = 1; n <= KORD; n++)
        k_prop<<<(NN * 32) / 256, 256>>>(n, lap, mf);
    k_softmax<<<(NN * 32) / 256, 256>>>(out);
}